// round 1
// baseline (speedup 1.0000x reference)
#include <cuda_runtime.h>

#define BETA   0.9f
#define NT     32                 // time steps
#define TILE_Q 256                // pooled (q) positions per CTA
#define NP     (2 * TILE_Q + 2)   // spk1 (p) positions incl. halo = 514
#define PSTR   520                // padded row stride for spike bytes
#define XCNT   1030               // x window floats needed
#define XPAD   1032

// [b][tile][t][o] partial FC sums
__device__ float g_partial[256 * 8 * NT * 2];

__device__ __forceinline__ float4 add4(float4 a, float4 b) {
    return make_float4(a.x + b.x, a.y + b.y, a.z + b.z, a.w + b.w);
}
__device__ __forceinline__ float4 max4(float4 a, float4 b) {
    return make_float4(fmaxf(a.x, b.x), fmaxf(a.y, b.y),
                       fmaxf(a.z, b.z), fmaxf(a.w, b.w));
}

__global__ __launch_bounds__(256) void snn_main(
    const float* __restrict__ x,     // [256,1,8192]
    const float* __restrict__ w1,    // [8,1,3]
    const float* __restrict__ b1,    // [8]
    const float* __restrict__ w2,    // [8,8,3]
    const float* __restrict__ b2,    // [8]
    const float* __restrict__ fcw,   // [2,16384]
    const float* __restrict__ th1p,
    const float* __restrict__ th2p)
{
    __shared__ __align__(16) float lut[3][256][8];  // 24 KB
    __shared__ float sx[XPAD];                       // 4.1 KB
    __shared__ unsigned char sb[NT][PSTR];           // 16.3 KB spike bytes
    __shared__ float psum[NT][8][2];                 // 2 KB

    const int blk  = blockIdx.x;
    const int b    = blk >> 3;      // sample
    const int tile = blk & 7;       // L-tile (8 per sample)
    const int tid  = threadIdx.x;
    const int q0   = tile * TILE_Q;
    const float th1 = *th1p;
    const float th2 = *th2p;

    // ---- Build conv2 byte-LUTs: lut[k][s][co] = sum_{ci in s} w2[co][ci][k]
    // (conv2 bias folded into tap-1 LUT; exactly one tap-1 term per position)
    for (int idx = tid; idx < 3 * 256; idx += 256) {
        const int k = idx >> 8;
        const int s = idx & 255;
        float acc[8];
        #pragma unroll
        for (int co = 0; co < 8; co++) acc[co] = (k == 1) ? b2[co] : 0.f;
        #pragma unroll
        for (int ci = 0; ci < 8; ci++) {
            if ((s >> ci) & 1) {
                #pragma unroll
                for (int co = 0; co < 8; co++)
                    acc[co] += w2[(co * 8 + ci) * 3 + k];
            }
        }
        #pragma unroll
        for (int co = 0; co < 8; co++) lut[k][s][co] = acc[co];
    }

    // ---- Load the x window this tile needs (zero-padded at edges)
    const int xbase = 4 * q0 - 3;
    const float* xb = x + b * 8192;
    for (int i = tid; i < XCNT; i += 256) {
        const int xg = xbase + i;
        sx[i] = (xg >= 0 && xg < 8192) ? xb[xg] : 0.f;
    }
    __syncthreads();

    // ---- Layer 1: conv1 + maxpool2 + 32-step LIF -> spike bytes in SMEM
    for (int ll = tid; ll < NP; ll += 256) {
        const int lg = (2 * q0 - 1) + ll;   // global spk1 position
        if (lg < 0 || lg >= 4096) {
            for (int t = 0; t < NT; t++) sb[t][ll] = 0;
            continue;
        }
        const float x0 = sx[2 * ll], x1 = sx[2 * ll + 1];
        const float x2 = sx[2 * ll + 2], x3 = sx[2 * ll + 3];
        float cur[8], m[8];
        #pragma unroll
        for (int c = 0; c < 8; c++) {
            const float wa = w1[3 * c], wb = w1[3 * c + 1], wc = w1[3 * c + 2];
            const float y0 = wa * x0 + wb * x1 + wc * x2;
            const float y1 = wa * x1 + wb * x2 + wc * x3;
            cur[c] = fmaxf(y0, y1) + b1[c];
            m[c] = 0.f;
        }
        bool sp[8];
        #pragma unroll
        for (int c = 0; c < 8; c++) sp[c] = false;
        for (int t = 0; t < NT; t++) {
            unsigned byte = 0;
            #pragma unroll
            for (int c = 0; c < 8; c++) {
                // reset uses carry-in mem > th  == previous step's spike
                float mm = BETA * m[c] + cur[c];
                if (sp[c]) mm -= th1;
                m[c] = mm;
                sp[c] = mm > th1;
                if (sp[c]) byte |= (1u << c);
            }
            sb[t][ll] = (unsigned char)byte;
        }
    }

    // ---- Per-thread FC weights (each thread owns q = q0+tid, co = 0..7)
    const int qg = q0 + tid;
    float fw0[8], fw1[8], m2[8];
    #pragma unroll
    for (int co = 0; co < 8; co++) {
        fw0[co] = fcw[co * 2048 + qg];
        fw1[co] = fcw[16384 + co * 2048 + qg];
        m2[co] = 0.f;
    }
    __syncthreads();

    const int lane = tid & 31, wrp = tid >> 5;
    const int p = 2 * tid;   // local index of s_{2q-1} in sb row

    // ---- Main time loop: conv2(LUT) + pool + LIF2 + FC partial
    #pragma unroll 1
    for (int t = 0; t < NT; t++) {
        const unsigned char* row = sb[t];
        const unsigned s0 = row[p], s1 = row[p + 1];
        const unsigned s2 = row[p + 2], s3 = row[p + 3];

        const float4* A0 = reinterpret_cast<const float4*>(lut[0][s0]);
        const float4* A1 = reinterpret_cast<const float4*>(lut[1][s1]);
        const float4* A2 = reinterpret_cast<const float4*>(lut[2][s2]);
        const float4* B0 = reinterpret_cast<const float4*>(lut[0][s1]);
        const float4* B1 = reinterpret_cast<const float4*>(lut[1][s2]);
        const float4* B2 = reinterpret_cast<const float4*>(lut[2][s3]);

        const float4 y0lo = add4(add4(A0[0], A1[0]), A2[0]);
        const float4 y0hi = add4(add4(A0[1], A1[1]), A2[1]);
        const float4 y1lo = add4(add4(B0[0], B1[0]), B2[0]);
        const float4 y1hi = add4(add4(B0[1], B1[1]), B2[1]);
        const float4 clo = max4(y0lo, y1lo);
        const float4 chi = max4(y0hi, y1hi);
        float cur2[8] = {clo.x, clo.y, clo.z, clo.w, chi.x, chi.y, chi.z, chi.w};

        float p0 = 0.f, p1 = 0.f;
        #pragma unroll
        for (int co = 0; co < 8; co++) {
            float mm = m2[co];
            const bool r = mm > th2;        // reset from carry-in mem
            mm = BETA * mm + cur2[co];
            if (r) mm -= th2;
            m2[co] = mm;
            if (mm > th2) { p0 += fw0[co]; p1 += fw1[co]; }
        }
        #pragma unroll
        for (int off = 16; off > 0; off >>= 1) {
            p0 += __shfl_down_sync(0xffffffffu, p0, off);
            p1 += __shfl_down_sync(0xffffffffu, p1, off);
        }
        if (lane == 0) { psum[t][wrp][0] = p0; psum[t][wrp][1] = p1; }
    }
    __syncthreads();

    if (tid < 64) {
        const int t = tid >> 1, o = tid & 1;
        float s = psum[t][0][o];
        #pragma unroll
        for (int w = 1; w < 8; w++) s += psum[t][w][o];
        g_partial[((b * 8 + tile) * NT + t) * 2 + o] = s;
    }
}

__global__ void snn_final(const float* __restrict__ fcb,
                          const float* __restrict__ thop,
                          float* __restrict__ out)
{
    const int b = threadIdx.x;
    if (b >= 256) return;
    const float tho = *thop;
    const float fb0 = fcb[0], fb1 = fcb[1];
    float m0 = 0.f, m1 = 0.f;
    for (int t = 0; t < NT; t++) {
        float s0 = 0.f, s1 = 0.f;
        #pragma unroll
        for (int tile = 0; tile < 8; tile++) {
            const float* gp = &g_partial[((b * 8 + tile) * NT + t) * 2];
            s0 += gp[0];
            s1 += gp[1];
        }
        const float c0 = s0 + fb0, c1 = s1 + fb1;
        const bool r0 = m0 > tho, r1 = m1 > tho;
        m0 = BETA * m0 + c0; if (r0) m0 -= tho;
        m1 = BETA * m1 + c1; if (r1) m1 -= tho;
        const int base = (t * 256 + b) * 2;
        out[base]     = (m0 > tho) ? 1.f : 0.f;   // spk_rec
        out[base + 1] = (m1 > tho) ? 1.f : 0.f;
        out[16384 + base]     = m0;               // mem_rec
        out[16384 + base + 1] = m1;
    }
}

extern "C" void kernel_launch(void* const* d_in, const int* in_sizes, int n_in,
                              void* d_out, int out_size)
{
    const float* x    = (const float*)d_in[0];
    const float* w1   = (const float*)d_in[1];
    const float* b1   = (const float*)d_in[2];
    const float* w2   = (const float*)d_in[3];
    const float* b2   = (const float*)d_in[4];
    const float* fcw  = (const float*)d_in[5];
    const float* fcb  = (const float*)d_in[6];
    const float* th1  = (const float*)d_in[7];
    const float* th2  = (const float*)d_in[8];
    const float* tho  = (const float*)d_in[9];
    float* out = (float*)d_out;

    snn_main<<<256 * 8, 256>>>(x, w1, b1, w2, b2, fcw, th1, th2);
    snn_final<<<1, 256>>>(fcb, tho, out);
}

// round 2
// speedup vs baseline: 1.3228x; 1.3228x over previous
#include <cuda_runtime.h>

#define BETA   0.9f
#define NT     32                 // time steps
#define TILE_Q 256                // pooled (q) positions per CTA
#define NTHR   512                // threads per CTA: (q, co-half)
#define NP     (2 * TILE_Q + 2)   // spk1 positions incl. halo = 514
#define PSTR   520                // padded row stride for spike bytes
#define XCNT   1030               // x window floats needed
#define XPAD   1032

// [b][tile][t][o] partial FC sums
__device__ float g_partial[256 * 8 * NT * 2];

__device__ __forceinline__ float4 add4(float4 a, float4 b) {
    return make_float4(a.x + b.x, a.y + b.y, a.z + b.z, a.w + b.w);
}
__device__ __forceinline__ float4 max4(float4 a, float4 b) {
    return make_float4(fmaxf(a.x, b.x), fmaxf(a.y, b.y),
                       fmaxf(a.z, b.z), fmaxf(a.w, b.w));
}

__global__ __launch_bounds__(NTHR) void snn_main(
    const float* __restrict__ x,     // [256,1,8192]
    const float* __restrict__ w1,    // [8,1,3]
    const float* __restrict__ b1,    // [8]
    const float* __restrict__ w2,    // [8,8,3]
    const float* __restrict__ b2,    // [8]
    const float* __restrict__ fcw,   // [2,16384]
    const float* __restrict__ th1p,
    const float* __restrict__ th2p)
{
    __shared__ __align__(16) float lut[3][256][8];   // 24 KB
    __shared__ float sx[XPAD];                        // 4.1 KB (aliased by psum later)
    __shared__ unsigned char sb[NT][PSTR];            // 16.3 KB spike bytes
    // psum[t][warp][o] aliases sx (sx dead after layer-1 phase): 32*16*2*4 = 4096 B
    float (*psum)[16][2] = reinterpret_cast<float (*)[16][2]>(sx);

    const int blk  = blockIdx.x;
    const int b    = blk >> 3;      // sample
    const int tile = blk & 7;       // L-tile (8 per sample)
    const int tid  = threadIdx.x;
    const int q0   = tile * TILE_Q;
    const float th1 = *th1p;
    const float th2 = *th2p;

    // ---- Build conv2 byte-LUTs: lut[k][s][co] = sum_{ci in s} w2[co][ci][k]
    // (conv2 bias folded into tap-1 LUT; exactly one tap-1 term per position)
    for (int idx = tid; idx < 3 * 256; idx += NTHR) {
        const int k = idx >> 8;
        const int s = idx & 255;
        float acc[8];
        #pragma unroll
        for (int co = 0; co < 8; co++) acc[co] = (k == 1) ? b2[co] : 0.f;
        #pragma unroll
        for (int ci = 0; ci < 8; ci++) {
            if ((s >> ci) & 1) {
                #pragma unroll
                for (int co = 0; co < 8; co++)
                    acc[co] += w2[(co * 8 + ci) * 3 + k];
            }
        }
        #pragma unroll
        for (int co = 0; co < 8; co++) lut[k][s][co] = acc[co];
    }

    // ---- Load the x window this tile needs (zero-padded at edges)
    const int xbase = 4 * q0 - 3;
    const float* xb = x + b * 8192;
    for (int i = tid; i < XCNT; i += NTHR) {
        const int xg = xbase + i;
        sx[i] = (xg >= 0 && xg < 8192) ? xb[xg] : 0.f;
    }
    __syncthreads();

    // ---- Layer 1: conv1 + maxpool2 + 32-step LIF -> spike bytes in SMEM
    for (int ll = tid; ll < NP; ll += NTHR) {
        const int lg = (2 * q0 - 1) + ll;   // global spk1 position
        if (lg < 0 || lg >= 4096) {
            for (int t = 0; t < NT; t++) sb[t][ll] = 0;
            continue;
        }
        const float x0 = sx[2 * ll], x1 = sx[2 * ll + 1];
        const float x2 = sx[2 * ll + 2], x3 = sx[2 * ll + 3];
        float cur[8], m[8];
        #pragma unroll
        for (int c = 0; c < 8; c++) {
            const float wa = w1[3 * c], wb = w1[3 * c + 1], wc = w1[3 * c + 2];
            const float y0 = wa * x0 + wb * x1 + wc * x2;
            const float y1 = wa * x1 + wb * x2 + wc * x3;
            cur[c] = fmaxf(y0, y1) + b1[c];
            m[c] = 0.f;
        }
        bool sp[8];
        #pragma unroll
        for (int c = 0; c < 8; c++) sp[c] = false;
        for (int t = 0; t < NT; t++) {
            unsigned byte = 0;
            #pragma unroll
            for (int c = 0; c < 8; c++) {
                // reset uses carry-in mem > th == previous step's spike
                float mm = BETA * m[c] + cur[c];
                if (sp[c]) mm -= th1;
                m[c] = mm;
                sp[c] = mm > th1;
                if (sp[c]) byte |= (1u << c);
            }
            sb[t][ll] = (unsigned char)byte;
        }
    }

    // ---- Thread role: q = tid>>1, half = tid&1 (co = 4*half .. 4*half+3)
    // Adjacent lanes alternate half -> LUT gather phases spread over 8 bank
    // slots instead of 4 (conflict mitigation).
    const int qloc = tid >> 1;
    const int h    = tid & 1;
    const int qg   = q0 + qloc;
    const int co0  = 4 * h;

    float fw0[4], fw1[4], m2[4];
    #pragma unroll
    for (int j = 0; j < 4; j++) {
        fw0[j] = fcw[(co0 + j) * 2048 + qg];
        fw1[j] = fcw[16384 + (co0 + j) * 2048 + qg];
        m2[j] = 0.f;
    }
    __syncthreads();

    const int lane = tid & 31, wrp = tid >> 5;
    const int p = 2 * qloc;   // local index of s_{2q-1} in sb row

    // ---- Main time loop: conv2(LUT, half rows) + pool + LIF2 + FC partial
    #pragma unroll 1
    for (int t = 0; t < NT; t++) {
        const unsigned char* row = sb[t];
        const unsigned s0 = row[p], s1 = row[p + 1];
        const unsigned s2 = row[p + 2], s3 = row[p + 3];

        const float4 A0 = *reinterpret_cast<const float4*>(&lut[0][s0][co0]);
        const float4 A1 = *reinterpret_cast<const float4*>(&lut[1][s1][co0]);
        const float4 A2 = *reinterpret_cast<const float4*>(&lut[2][s2][co0]);
        const float4 B0 = *reinterpret_cast<const float4*>(&lut[0][s1][co0]);
        const float4 B1 = *reinterpret_cast<const float4*>(&lut[1][s2][co0]);
        const float4 B2 = *reinterpret_cast<const float4*>(&lut[2][s3][co0]);

        const float4 y0 = add4(add4(A0, A1), A2);
        const float4 y1 = add4(add4(B0, B1), B2);
        const float4 cv = max4(y0, y1);
        float cur2[4] = {cv.x, cv.y, cv.z, cv.w};

        float p0 = 0.f, p1 = 0.f;
        #pragma unroll
        for (int j = 0; j < 4; j++) {
            float mm = m2[j];
            const bool r = mm > th2;        // reset from carry-in mem
            mm = BETA * mm + cur2[j];
            if (r) mm -= th2;
            m2[j] = mm;
            if (mm > th2) { p0 += fw0[j]; p1 += fw1[j]; }
        }
        #pragma unroll
        for (int off = 16; off > 0; off >>= 1) {
            p0 += __shfl_down_sync(0xffffffffu, p0, off);
            p1 += __shfl_down_sync(0xffffffffu, p1, off);
        }
        if (lane == 0) { psum[t][wrp][0] = p0; psum[t][wrp][1] = p1; }
    }
    __syncthreads();

    if (tid < 64) {
        const int t = tid >> 1, o = tid & 1;
        float s = psum[t][0][o];
        #pragma unroll
        for (int w = 1; w < 16; w++) s += psum[t][w][o];
        g_partial[((b * 8 + tile) * NT + t) * 2 + o] = s;
    }
}

__global__ __launch_bounds__(64) void snn_final(
    const float* __restrict__ fcb,
    const float* __restrict__ thop,
    float* __restrict__ out)
{
    __shared__ float sm[NT][2];
    const int b = blockIdx.x;
    const int tid = threadIdx.x;

    // 64 threads: (t, o) each sums its 8 tile partials in parallel
    {
        const int t = tid >> 1, o = tid & 1;
        float s = 0.f;
        #pragma unroll
        for (int tile = 0; tile < 8; tile++)
            s += g_partial[((b * 8 + tile) * NT + t) * 2 + o];
        sm[t][o] = s;
    }
    __syncthreads();

    if (tid < 2) {
        const int o = tid;
        const float tho = *thop;
        const float fb = fcb[o];
        float m = 0.f;
        for (int t = 0; t < NT; t++) {
            const float c = sm[t][o] + fb;
            const bool r = m > tho;
            m = BETA * m + c;
            if (r) m -= tho;
            const int base = (t * 256 + b) * 2 + o;
            out[base] = (m > tho) ? 1.f : 0.f;    // spk_rec
            out[16384 + base] = m;                // mem_rec
        }
    }
}

extern "C" void kernel_launch(void* const* d_in, const int* in_sizes, int n_in,
                              void* d_out, int out_size)
{
    const float* x    = (const float*)d_in[0];
    const float* w1   = (const float*)d_in[1];
    const float* b1   = (const float*)d_in[2];
    const float* w2   = (const float*)d_in[3];
    const float* b2   = (const float*)d_in[4];
    const float* fcw  = (const float*)d_in[5];
    const float* fcb  = (const float*)d_in[6];
    const float* th1  = (const float*)d_in[7];
    const float* th2  = (const float*)d_in[8];
    const float* tho  = (const float*)d_in[9];
    float* out = (float*)d_out;

    snn_main<<<256 * 8, NTHR>>>(x, w1, b1, w2, b2, fcw, th1, th2);
    snn_final<<<256, 64>>>(fcb, tho, out);
}